// round 1
// baseline (speedup 1.0000x reference)
#include <cuda_runtime.h>

// Problem constants (fixed shapes: x = (4,64,256,256) f32, stoken = 16)
#define Bn 4
#define Cc 64
#define Hh 256
#define Ww 256
#define NH 16      // superpixel grid 16x16
#define NS 256     // nH*nW
#define PP 65536   // H*W

// Scratch (allocation-free: __device__ globals)
__device__ float g_cent[Bn * NS * Cc];
__device__ float g_num [Bn * NS * Cc];
__device__ float g_den [Bn * NS];

// ---------------------------------------------------------------------------
// Zero-fill the 256MB output with float4 stores (pure streaming writes)
// ---------------------------------------------------------------------------
__global__ __launch_bounds__(256) void fill_zero_kernel(float4* __restrict__ A) {
    size_t idx = (size_t)blockIdx.x * 256 + threadIdx.x;
    A[idx] = make_float4(0.f, 0.f, 0.f, 0.f);
}

// ---------------------------------------------------------------------------
// Initial centroids: block mean over each 16x16 block. Also zeroes scratch.
// grid (NS, B), 256 threads. tid = c*4 + g ; thread sums 64 pixels (stride 4).
// ---------------------------------------------------------------------------
__global__ __launch_bounds__(256) void init_cent_kernel(const float* __restrict__ x) {
    int b = blockIdx.y, s = blockIdx.x;
    int bi = s >> 4, bj = s & 15;
    int tid = threadIdx.x;
    int c = tid >> 2, g = tid & 3;
    const float* fc = x + (((size_t)b * Cc + c) << 16);
    int base = (bi * 16) * Ww + bj * 16;
    float acc = 0.f;
    #pragma unroll 8
    for (int i = g; i < 256; i += 4)
        acc += fc[base + ((i >> 4) << 8) + (i & 15)];
    __shared__ float part[256];
    part[tid] = acc;
    __syncthreads();
    if (tid < 64) {
        int o4 = tid * 4;
        float v = part[o4] + part[o4 + 1] + part[o4 + 2] + part[o4 + 3];
        int idx = (b * NS + s) * Cc + tid;
        g_cent[idx] = v * (1.f / 256.f);
        g_num[idx]  = 0.f;
    }
    if (tid == 64) g_den[b * NS + s] = 0.f;
}

// ---------------------------------------------------------------------------
// Affinity pass. One CTA per (b, 16x16 pixel block); 256 threads = 256 pixels.
// PASS 0: fused centroid-update reduction (num/den) with global atomics.
// PASS 1: scatter affinities into dense output A (rest stays zero from fill).
// ---------------------------------------------------------------------------
template <int PASS>
__global__ __launch_bounds__(256) void affinity_kernel(const float* __restrict__ x,
                                                       float* __restrict__ A) {
    int b = blockIdx.y, sblk = blockIdx.x;
    int bi = sblk >> 4, bj = sblk & 15;
    int tid = threadIdx.x;

    __shared__ float cent_sm[9][64];
    __shared__ float c2_sm[9];
    __shared__ int   cand_s[9];
    __shared__ int   cand_v[9];

    if (tid < 9) {
        int ci = bi + tid / 3 - 1, cj = bj + tid % 3 - 1;
        int v = (ci >= 0 && ci < NH && cj >= 0 && cj < NH);
        cand_v[tid] = v;
        cand_s[tid] = v ? ci * NH + cj : 0;
    }
    __syncthreads();
    for (int i = tid; i < 9 * 64; i += 256) {
        int k = i >> 6, c = i & 63;
        cent_sm[k][c] = g_cent[(b * NS + cand_s[k]) * Cc + c];
    }
    __syncthreads();
    if (tid < 9) {
        float s2 = 0.f;
        #pragma unroll 8
        for (int c = 0; c < 64; c++) { float v = cent_sm[tid][c]; s2 += v * v; }
        c2_sm[tid] = s2;
    }
    __syncthreads();

    // ---- per-pixel dots over 64 channels against 9 staged centroids ----
    int ly = tid >> 4, lx = tid & 15;
    int p = ((bi * 16 + ly) << 8) + bj * 16 + lx;
    const float* fb = x + (((size_t)b * Cc) << 16) + p;
    float f2 = 0.f;
    float dot[9];
    #pragma unroll
    for (int k = 0; k < 9; k++) dot[k] = 0.f;
    #pragma unroll 4
    for (int c = 0; c < 64; c++) {
        float f = fb[(size_t)c << 16];
        f2 = fmaf(f, f, f2);
        #pragma unroll
        for (int k = 0; k < 9; k++) dot[k] = fmaf(f, cent_sm[k][c], dot[k]);
    }

    // ---- masked softmax over 9 candidates ----
    float aff[9];
    float mx = -3.0e38f;
    #pragma unroll
    for (int k = 0; k < 9; k++) {
        float d = f2 + c2_sm[k] - 2.f * dot[k];
        aff[k] = cand_v[k] ? -d : -1e30f;
        mx = fmaxf(mx, aff[k]);
    }
    float ssum = 0.f;
    #pragma unroll
    for (int k = 0; k < 9; k++) { float e = __expf(aff[k] - mx); aff[k] = e; ssum += e; }
    float rs = 1.f / ssum;
    #pragma unroll
    for (int k = 0; k < 9; k++) aff[k] = cand_v[k] ? aff[k] * rs : 0.f;

    if (PASS == 0) {
        // den: warp reduce each of 9 affinities over the 256 pixels
        __shared__ float denpart[8][9];
        #pragma unroll
        for (int k = 0; k < 9; k++) {
            float v = aff[k];
            v += __shfl_xor_sync(0xffffffffu, v, 16);
            v += __shfl_xor_sync(0xffffffffu, v, 8);
            v += __shfl_xor_sync(0xffffffffu, v, 4);
            v += __shfl_xor_sync(0xffffffffu, v, 2);
            v += __shfl_xor_sync(0xffffffffu, v, 1);
            if ((tid & 31) == 0) denpart[tid >> 5][k] = v;
        }
        __shared__ float aff_sm[9][256];
        #pragma unroll
        for (int k = 0; k < 9; k++) aff_sm[k][tid] = aff[k];
        __syncthreads();

        // num[k][c] = sum_p aff[k][p] * feats[c][p] ; thread = (c, g=pixel group)
        int c = tid >> 2, g = tid & 3;
        const float* fc = x + (((size_t)b * Cc + c) << 16);
        int base = ((bi * 16) << 8) + bj * 16;
        float acc[9];
        #pragma unroll
        for (int k = 0; k < 9; k++) acc[k] = 0.f;
        for (int i = g; i < 256; i += 4) {
            float f = fc[base + ((i >> 4) << 8) + (i & 15)];
            #pragma unroll
            for (int k = 0; k < 9; k++) acc[k] = fmaf(aff_sm[k][i], f, acc[k]);
        }
        __shared__ float part[9][256];
        #pragma unroll
        for (int k = 0; k < 9; k++) part[k][tid] = acc[k];
        __syncthreads();

        for (int i = tid; i < 9 * 64; i += 256) {
            int k = i >> 6, c2i = i & 63;
            if (cand_v[k]) {
                int o4 = c2i * 4;
                float v = part[k][o4] + part[k][o4 + 1] + part[k][o4 + 2] + part[k][o4 + 3];
                atomicAdd(&g_num[(b * NS + cand_s[k]) * Cc + c2i], v);
            }
        }
        if (tid < 9 && cand_v[tid]) {
            float v = 0.f;
            #pragma unroll
            for (int w = 0; w < 8; w++) v += denpart[w][tid];
            atomicAdd(&g_den[b * NS + cand_s[tid]], v);
        }
    } else {
        // scatter affinities into dense A: A[b, cand_s[k], p] = aff[k]
        #pragma unroll
        for (int k = 0; k < 9; k++) {
            if (cand_v[k])
                A[(((size_t)b * NS + cand_s[k]) << 16) + p] = aff[k];
        }
    }
}

// ---------------------------------------------------------------------------
// cent = num / (den + 1e-16)
// ---------------------------------------------------------------------------
__global__ __launch_bounds__(256) void update_cent_kernel() {
    int i = blockIdx.x * 256 + threadIdx.x;
    if (i < Bn * NS * Cc) {
        int bs = i >> 6;
        g_cent[i] = g_num[i] / (g_den[bs] + 1e-16f);
    }
}

extern "C" void kernel_launch(void* const* d_in, const int* in_sizes, int n_in,
                              void* d_out, int out_size) {
    const float* x = (const float*)d_in[0];
    float* A = (float*)d_out;

    // 1) zero the 256MB dense output
    int n4 = out_size / 4;                        // float4 count = 16,777,216
    fill_zero_kernel<<<n4 / 256, 256>>>((float4*)A);

    dim3 grid(NS, Bn);
    // 2) initial centroids (block means) + zero scratch accumulators
    init_cent_kernel<<<grid, 256>>>(x);
    // 3) pass 0: affinities + fused centroid-update reduction
    affinity_kernel<0><<<grid, 256>>>(x, A);
    // 4) finalize centroids
    update_cent_kernel<<<(Bn * NS * Cc + 255) / 256, 256>>>();
    // 5) pass 1: affinities, scattered into dense A
    affinity_kernel<1><<<grid, 256>>>(x, A);
}